// round 14
// baseline (speedup 1.0000x reference)
#include <cuda_runtime.h>
#include <cuda_bf16.h>
#include <cstdint>

#define NN 50000
#define EE 800000
#define DD 128
#define NHH 8

// ---------------- device scratch (no allocations allowed) ----------------
__device__ __align__(16) float g_V[NN * DD];     // H @ Wv^T
__device__ __align__(16) float g_agg[NN * DD];   // aggregated messages
__device__ __align__(16) float g_Adst[NN * NHH]; // H @ (W4 W1)^T
__device__ __align__(16) float g_Asrc[NN * NHH]; // H @ (W4 W2)^T
__device__ __align__(16) float g_Wa[16 * DD];    // rows 0-7: W4@W1, rows 8-15: W4@W2
__device__ float g_c[NHH];                       // W3 . W4[h]
__device__ int   g_deg[NN];
__device__ int   g_offs[NN + 1];
__device__ int   g_epos[EE];                     // per-edge slot within its dst bucket
__device__ __align__(16) float4 g_edge[EE];      // .x=src bits, .y=P, .z=De
__device__ __align__(16) float g_exp[EE * NHH];

// ---------------- mma.sync bf16 split-precision GEMM machinery ----------------
// smem tiles: 128 rows x 64 bf16, pitch 72 bf16 (144B) -> fragment loads conflict-free
#define TPITCHB 144                    // bytes per tile row
#define T_AHI 0
#define T_ALO 18432
#define T_BHI 36864
#define T_BLO 55296
#define SM_GEMM 73728                  // 4 tiles; also >= 128*132*4 stage for k_out

__device__ __forceinline__ void mma16816(float* c, const uint32_t* a, const uint32_t* b) {
    asm volatile(
        "mma.sync.aligned.m16n8k16.row.col.f32.bf16.bf16.f32 "
        "{%0,%1,%2,%3}, {%4,%5,%6,%7}, {%8,%9}, {%0,%1,%2,%3};\n"
        : "+f"(c[0]), "+f"(c[1]), "+f"(c[2]), "+f"(c[3])
        : "r"(a[0]), "r"(a[1]), "r"(a[2]), "r"(a[3]), "r"(b[0]), "r"(b[1]));
}

// fetch 128x64 fp32 tile into 8 float4 regs/thread (256 threads)
__device__ __forceinline__ void g_fetch(float4* r, const float* __restrict__ G,
                                        int row0, int nrows, int kcol0) {
    int t = threadIdx.x;
    #pragma unroll
    for (int i = 0; i < 8; i++) {
        int f = t + i * 256;           // 2048 float4s
        int row = f >> 4, kq = f & 15;
        float4 v = make_float4(0.f, 0.f, 0.f, 0.f);
        if (row0 + row < nrows)
            v = *(const float4*)(G + (size_t)(row0 + row) * DD + kcol0 + kq * 4);
        r[i] = v;
    }
}

// convert regs -> bf16 hi/lo into padded smem
__device__ __forceinline__ void s_store(char* sm, int oh, int ol, const float4* r) {
    int t = threadIdx.x;
    #pragma unroll
    for (int i = 0; i < 8; i++) {
        int f = t + i * 256;
        int row = f >> 4, kq = f & 15;
        float xs[4] = {r[i].x, r[i].y, r[i].z, r[i].w};
        uint16_t hb[4], lb[4];
        #pragma unroll
        for (int q = 0; q < 4; q++) {
            __nv_bfloat16 h = __float2bfloat16(xs[q]);
            __nv_bfloat16 l = __float2bfloat16(xs[q] - __bfloat162float(h));
            hb[q] = __nv_bfloat16_raw(h).x;
            lb[q] = __nv_bfloat16_raw(l).x;
        }
        char* ph = sm + oh + row * TPITCHB + kq * 8;
        char* pl = sm + ol + row * TPITCHB + kq * 8;
        *(uint32_t*)ph       = (uint32_t)hb[1] << 16 | hb[0];
        *(uint32_t*)(ph + 4) = (uint32_t)hb[3] << 16 | hb[2];
        *(uint32_t*)pl       = (uint32_t)lb[1] << 16 | lb[0];
        *(uint32_t*)(pl + 4) = (uint32_t)lb[3] << 16 | lb[2];
    }
}

// one K=64 chunk of split MMAs; acc[2][8][4] per warp (warp tile 32x64)
__device__ __forceinline__ void mma_chunk(const char* sm, float acc[2][8][4],
                                          int warp_m, int warp_n, int lane) {
    int lr = lane >> 2, lc = lane & 3;
    #pragma unroll
    for (int ks = 0; ks < 4; ks++) {
        uint32_t ah[2][4], al[2][4], bh[8][2], bl[8][2];
        int kb = (ks * 16 + lc * 2) * 2;     // byte offset of k pair
        #pragma unroll
        for (int mt = 0; mt < 2; mt++) {
            int r = warp_m * 32 + mt * 16 + lr;
            const char* p = sm + T_AHI + r * TPITCHB + kb;
            ah[mt][0] = *(const uint32_t*)p;
            ah[mt][1] = *(const uint32_t*)(p + 8 * TPITCHB);
            ah[mt][2] = *(const uint32_t*)(p + 16);
            ah[mt][3] = *(const uint32_t*)(p + 8 * TPITCHB + 16);
            const char* q = sm + T_ALO + r * TPITCHB + kb;
            al[mt][0] = *(const uint32_t*)q;
            al[mt][1] = *(const uint32_t*)(q + 8 * TPITCHB);
            al[mt][2] = *(const uint32_t*)(q + 16);
            al[mt][3] = *(const uint32_t*)(q + 8 * TPITCHB + 16);
        }
        #pragma unroll
        for (int nt = 0; nt < 8; nt++) {
            int r = warp_n * 64 + nt * 8 + lr;
            const char* p = sm + T_BHI + r * TPITCHB + kb;
            bh[nt][0] = *(const uint32_t*)p;
            bh[nt][1] = *(const uint32_t*)(p + 16);
            const char* q = sm + T_BLO + r * TPITCHB + kb;
            bl[nt][0] = *(const uint32_t*)q;
            bl[nt][1] = *(const uint32_t*)(q + 16);
        }
        #pragma unroll
        for (int mt = 0; mt < 2; mt++)
            #pragma unroll
            for (int nt = 0; nt < 8; nt++) {
                mma16816(acc[mt][nt], ah[mt], bh[nt]);
                mma16816(acc[mt][nt], ah[mt], bl[nt]);
                mma16816(acc[mt][nt], al[mt], bh[nt]);
            }
    }
}

// ---------------- V = H @ Wv^T (tensor) + attn projection (fp32, L2-warm) ------
#define WAPITCH 130
__global__ void __launch_bounds__(256, 1) k_gemm_v(const float* __restrict__ H,
                                                   const float* __restrict__ Wv, int n) {
    extern __shared__ __align__(16) char sm[];
    __shared__ float s_Wa[16 * WAPITCH];
    int tid = threadIdx.x, wid = tid >> 5, lane = tid & 31;
    int warp_m = wid >> 1, warp_n = wid & 1;
    int m0 = blockIdx.x * 128;

    // stage Wa (16x128) into padded smem
    #pragma unroll
    for (int i = 0; i < 8; i++) {
        int f = tid + i * 256;    // 2048 elements
        int wr = f >> 7, k = f & 127;
        s_Wa[wr * WAPITCH + k] = g_Wa[wr * DD + k];
    }

    float acc[2][8][4];
    #pragma unroll
    for (int mt = 0; mt < 2; mt++)
        #pragma unroll
        for (int nt = 0; nt < 8; nt++)
            #pragma unroll
            for (int q = 0; q < 4; q++) acc[mt][nt][q] = 0.f;

    float4 ra[8], rb[8];
    g_fetch(ra, H, m0, n, 0);
    g_fetch(rb, Wv, 0, 128, 0);
    for (int c = 0; c < 2; c++) {
        if (c > 0) __syncthreads();          // mma of c-1 done before overwrite
        s_store(sm, T_AHI, T_ALO, ra);
        s_store(sm, T_BHI, T_BLO, rb);
        if (c < 1) {                         // prefetch next chunk (hidden behind mma)
            g_fetch(ra, H, m0, n, 64);
            g_fetch(rb, Wv, 0, 128, 64);
        }
        __syncthreads();
        mma_chunk(sm, acc, warp_m, warp_n, lane);
    }

    int lr = lane >> 2, lc = lane & 3;
    #pragma unroll
    for (int mt = 0; mt < 2; mt++) {
        int r0 = m0 + warp_m * 32 + mt * 16 + lr;
        #pragma unroll
        for (int nt = 0; nt < 8; nt++) {
            int cc = warp_n * 64 + nt * 8 + lc * 2;
            if (r0 < n)
                *(float2*)(g_V + (size_t)r0 * DD + cc) =
                    make_float2(acc[mt][nt][0], acc[mt][nt][1]);
            if (r0 + 8 < n)
                *(float2*)(g_V + (size_t)(r0 + 8) * DD + cc) =
                    make_float2(acc[mt][nt][2], acc[mt][nt][3]);
        }
    }

    // attention projection: thread pair (r, half) dots H row r (L2-warm) with 8 Wa rows
    int r = tid >> 1, half = tid & 1;
    int grow = m0 + r;
    if (grow < n) {
        float acc2[8];
        #pragma unroll
        for (int h = 0; h < 8; h++) acc2[h] = 0.f;
        const float4* hrow = (const float4*)(H + (size_t)grow * DD);
        const float* wbase = s_Wa + half * 8 * WAPITCH;
        #pragma unroll 4
        for (int kq = 0; kq < 32; kq++) {
            float4 hv = hrow[kq];
            #pragma unroll
            for (int h = 0; h < 8; h++) {
                const float* wr = wbase + h * WAPITCH + kq * 4;
                acc2[h] = fmaf(hv.x, wr[0], acc2[h]);
                acc2[h] = fmaf(hv.y, wr[1], acc2[h]);
                acc2[h] = fmaf(hv.z, wr[2], acc2[h]);
                acc2[h] = fmaf(hv.w, wr[3], acc2[h]);
            }
        }
        float* dp = half ? (g_Asrc + (size_t)grow * 8) : (g_Adst + (size_t)grow * 8);
        #pragma unroll
        for (int h = 0; h < 8; h++) dp[h] = acc2[h];
    }
}

// --------- out = LN([agg|H] @ [Wout|resw]^T + bias), K=256, tensor pipe ----------
__global__ void __launch_bounds__(256, 1) k_gemm_out(const float* __restrict__ H,
                                                     const float* __restrict__ Wout,
                                                     const float* __restrict__ Woutb,
                                                     const float* __restrict__ resw,
                                                     const float* __restrict__ resb,
                                                     const float* __restrict__ lng,
                                                     const float* __restrict__ lnb,
                                                     float* __restrict__ out, int n) {
    extern __shared__ __align__(16) char sm[];
    __shared__ __align__(16) float s_wb[128], s_g[128], s_b[128];
    int tid = threadIdx.x, wid = tid >> 5, lane = tid & 31;
    int warp_m = wid >> 1, warp_n = wid & 1;
    int m0 = blockIdx.x * 128;

    if (tid < 128) {
        s_wb[tid] = Woutb[tid] + resb[tid];
        s_g[tid] = lng[tid];
        s_b[tid] = lnb[tid];
    }

    float acc[2][8][4];
    #pragma unroll
    for (int mt = 0; mt < 2; mt++)
        #pragma unroll
        for (int nt = 0; nt < 8; nt++)
            #pragma unroll
            for (int q = 0; q < 4; q++) acc[mt][nt][q] = 0.f;

    const float* Asrc[4] = {g_agg, g_agg, H, H};
    const float* Bsrc[4] = {Wout, Wout, resw, resw};

    float4 ra[8], rb[8];
    g_fetch(ra, Asrc[0], m0, n, 0);
    g_fetch(rb, Bsrc[0], 0, 128, 0);
    for (int c = 0; c < 4; c++) {
        if (c > 0) __syncthreads();
        s_store(sm, T_AHI, T_ALO, ra);
        s_store(sm, T_BHI, T_BLO, rb);
        if (c < 3) {
            int kcol = ((c + 1) & 1) * 64;
            g_fetch(ra, Asrc[c + 1], m0, n, kcol);
            g_fetch(rb, Bsrc[c + 1], 0, 128, kcol);
        }
        __syncthreads();
        mma_chunk(sm, acc, warp_m, warp_n, lane);
    }
    __syncthreads();   // all mma reads done before stg overwrite

    // stage pre-LN rows in smem (reuse tile space), pitch 132 floats
    float* stg = (float*)sm;
    int lr = lane >> 2, lc = lane & 3;
    #pragma unroll
    for (int mt = 0; mt < 2; mt++) {
        int r0 = warp_m * 32 + mt * 16 + lr;
        #pragma unroll
        for (int nt = 0; nt < 8; nt++) {
            int cc = warp_n * 64 + nt * 8 + lc * 2;
            *(float2*)(stg + r0 * 132 + cc) = make_float2(acc[mt][nt][0], acc[mt][nt][1]);
            *(float2*)(stg + (r0 + 8) * 132 + cc) = make_float2(acc[mt][nt][2], acc[mt][nt][3]);
        }
    }
    __syncthreads();

    // LN: warp w handles rows [w*16, w*16+16)
    float4 wb4 = *(const float4*)(s_wb + lane * 4);
    float4 g4  = *(const float4*)(s_g + lane * 4);
    float4 b4  = *(const float4*)(s_b + lane * 4);
    for (int r = wid * 16; r < wid * 16 + 16; r++) {
        int grow = m0 + r;
        float4 v = *(const float4*)(stg + r * 132 + lane * 4);
        v.x += wb4.x; v.y += wb4.y; v.z += wb4.z; v.w += wb4.w;
        float s = v.x + v.y + v.z + v.w;
        float q = v.x * v.x + v.y * v.y + v.z * v.z + v.w * v.w;
        #pragma unroll
        for (int o = 16; o; o >>= 1) {
            s += __shfl_xor_sync(0xffffffffu, s, o);
            q += __shfl_xor_sync(0xffffffffu, q, o);
        }
        float mu  = s * (1.0f / 128.0f);
        float var = q * (1.0f / 128.0f) - mu * mu;
        float inv = rsqrtf(var + 1e-5f);
        if (grow < n) {
            float4 o4;
            o4.x = (v.x - mu) * inv * g4.x + b4.x;
            o4.y = (v.y - mu) * inv * g4.y + b4.y;
            o4.z = (v.z - mu) * inv * g4.z + b4.z;
            o4.w = (v.w - mu) * inv * g4.w + b4.w;
            *(float4*)(out + (size_t)grow * DD + lane * 4) = o4;
        }
    }
}

// ---------------- prep: blocks 0-7 compute Wa/c, blocks 8+ zero counters ------
__global__ void k_prep(const float* __restrict__ W1, const float* __restrict__ W2,
                       const float* __restrict__ W3, const float* __restrict__ W4,
                       int n) {
    if (blockIdx.x < 8) {
        int t = blockIdx.x * 256 + threadIdx.x;
        if (t < 16 * DD) {
            int h16 = t >> 7;
            int d = t & 127;
            const float* Wsel = (h16 < 8) ? W1 : W2;
            int h = h16 & 7;
            float s = 0.f;
            for (int k = 0; k < DD; k++)
                s = fmaf(W4[h * DD + k], Wsel[k * DD + d], s);
            g_Wa[t] = s;
        }
        if (t < NHH) {
            float s = 0.f;
            for (int j = 0; j < DD; j++)
                s = fmaf(W3[j], W4[t * DD + j], s);
            g_c[t] = s;
        }
    } else {
        int i = (blockIdx.x - 8) * 256 + threadIdx.x;
        if (i < n) g_deg[i] = 0;
    }
}

// edge_index is int32 (JAX x64 disabled; jnp.int64 silently downcasts).
// Record each edge's slot within its dst bucket -> scatter needs no atomics.
__global__ void k_hist(const int* __restrict__ ei, int e, int n) {
    int i = blockIdx.x * blockDim.x + threadIdx.x;
    if (i < e) {
        int dst = ei[e + i];
        dst = min(max(dst, 0), n - 1);
        g_epos[i] = atomicAdd(&g_deg[dst], 1);
    }
}

// single-block smem-tiled coarsened exclusive scan: g_deg -> g_offs
#define STILE 8192
__global__ void __launch_bounds__(1024) k_scan(int n) {
    __shared__ __align__(16) int sd[STILE];
    __shared__ int wsum[32];
    __shared__ int s_carry;
    int tid = threadIdx.x, lane = tid & 31, wid = tid >> 5;
    if (tid == 0) s_carry = 0;
    __syncthreads();

    for (int base = 0; base < n; base += STILE) {
        #pragma unroll
        for (int k = 0; k < 8; k++) {
            int i = base + tid + k * 1024;
            sd[tid + k * 1024] = (i < n) ? g_deg[i] : 0;
        }
        __syncthreads();

        int4 v0 = *(const int4*)&sd[tid * 8];
        int4 v1 = *(const int4*)&sd[tid * 8 + 4];
        int loc[8] = {v0.x, v0.y, v0.z, v0.w, v1.x, v1.y, v1.z, v1.w};
        int s = 0;
        #pragma unroll
        for (int k = 0; k < 8; k++) s += loc[k];

        int x = s;
        #pragma unroll
        for (int o = 1; o < 32; o <<= 1) {
            int y = __shfl_up_sync(0xffffffffu, x, o);
            if (lane >= o) x += y;
        }
        if (lane == 31) wsum[wid] = x;
        __syncthreads();
        if (wid == 0) {
            int w = wsum[lane];
            #pragma unroll
            for (int o = 1; o < 32; o <<= 1) {
                int y = __shfl_up_sync(0xffffffffu, w, o);
                if (lane >= o) w += y;
            }
            wsum[lane] = w;
        }
        __syncthreads();

        int run = x - s + (wid ? wsum[wid - 1] : 0) + s_carry;
        int4 o0, o1;
        o0.x = run; run += loc[0];
        o0.y = run; run += loc[1];
        o0.z = run; run += loc[2];
        o0.w = run; run += loc[3];
        o1.x = run; run += loc[4];
        o1.y = run; run += loc[5];
        o1.z = run; run += loc[6];
        o1.w = run; run += loc[7];
        *(int4*)&sd[tid * 8]     = o0;
        *(int4*)&sd[tid * 8 + 4] = o1;
        __syncthreads();
        if (tid == 1023) s_carry = run;

        #pragma unroll
        for (int k = 0; k < 8; k++) {
            int i = base + tid + k * 1024;
            if (i < n) g_offs[i] = sd[tid + k * 1024];
        }
        __syncthreads();
    }
    if (tid == 0) g_offs[n] = s_carry;
}

// atomic-free scatter: slot from g_epos; single 16B packed store per edge
__global__ void k_scatter(const int* __restrict__ ei,
                          const float* __restrict__ P, const float* __restrict__ DT,
                          int e, int n) {
    int i = blockIdx.x * blockDim.x + threadIdx.x;
    if (i < e) {
        int src = ei[i];
        int dst = ei[e + i];
        src = min(max(src, 0), n - 1);
        dst = min(max(dst, 0), n - 1);
        int j = g_offs[dst] + g_epos[i];
        if (j >= 0 && j < e)
            g_edge[j] = make_float4(__int_as_float(src), P[i], DT[i], 0.f);
    }
}

// ------- per-dst-node attention + aggregation (TWO warps per node) -------
__global__ void __launch_bounds__(256) k_attn(int n) {
    __shared__ float  s_p[4][2][NHH];
    __shared__ __align__(16) float4 s_acc[4][32];
    int tid = threadIdx.x, wid = tid >> 5, lane = tid & 31;
    int local = wid >> 1, sub = wid & 1;
    int gw = blockIdx.x * 4 + local;
    bool act = gw < n;
    int beg = 0, end = 0;
    if (act) { beg = g_offs[gw]; end = g_offs[gw + 1]; }

    float adst[8], cv[8];
    #pragma unroll
    for (int h = 0; h < 8; h++) cv[h] = g_c[h];
    if (act)
        #pragma unroll
        for (int h = 0; h < 8; h++) adst[h] = g_Adst[(size_t)gw * 8 + h];

    // pass 1: exp(logit) + per-head partial sums (softmax shift algebraically free;
    // logits are O(10) << 88 so unshifted fp32 exp cannot overflow)
    float sm8[8];
    #pragma unroll
    for (int h = 0; h < 8; h++) sm8[h] = 0.f;
    if (act) {
        for (int j = beg + sub * 32 + lane; j < end; j += 64) {
            float4 ed = g_edge[j];
            int s = __float_as_int(ed.x);
            float p = ed.y, dt = ed.z;
            const float4* as4 = (const float4*)(g_Asrc + (size_t)s * 8);
            float4 a0 = as4[0], a1 = as4[1];
            float asv[8] = {a0.x, a0.y, a0.z, a0.w, a1.x, a1.y, a1.z, a1.w};
            float ex[8];
            #pragma unroll
            for (int h = 0; h < 8; h++) {
                float l = adst[h] + asv[h] + p * cv[h] + dt;
                l = (l >= 0.f) ? l : 0.2f * l;
                ex[h] = __expf(l);
                sm8[h] += ex[h];
            }
            *(float4*)(g_exp + (size_t)j * 8)     = make_float4(ex[0], ex[1], ex[2], ex[3]);
            *(float4*)(g_exp + (size_t)j * 8 + 4) = make_float4(ex[4], ex[5], ex[6], ex[7]);
        }
    }
    #pragma unroll
    for (int h = 0; h < 8; h++)
        #pragma unroll
        for (int o = 16; o; o >>= 1)
            sm8[h] += __shfl_xor_sync(0xffffffffu, sm8[h], o);
    if (lane < 8) s_p[local][sub][lane] = sm8[lane];
    __syncthreads();

    // pass 2: weighted aggregation; lane covers dims [lane*4,+4), head = lane>>2;
    // warp sub takes edges j = beg+sub, step 2
    int h = lane >> 2;
    float4 acc = make_float4(0.f, 0.f, 0.f, 0.f);
    if (act) {
        float dsel = s_p[local][0][h] + s_p[local][1][h];
        float ri = __fdividef(1.0f, dsel + 1e-12f);
        const float4* Vv = (const float4*)g_V;
        #pragma unroll 4
        for (int j = beg + sub; j < end; j += 2) {
            float a = g_exp[(size_t)j * 8 + h] * ri;
            int s = __float_as_int(g_edge[j].x);
            float4 v = Vv[(size_t)s * 32 + lane];
            acc.x = fmaf(a, v.x, acc.x);
            acc.y = fmaf(a, v.y, acc.y);
            acc.z = fmaf(a, v.z, acc.z);
            acc.w = fmaf(a, v.w, acc.w);
        }
    }
    if (sub == 1) s_acc[local][lane] = acc;
    __syncthreads();
    if (act && sub == 0) {
        float4 o = s_acc[local][lane];
        acc.x += o.x; acc.y += o.y; acc.z += o.z; acc.w += o.w;
        *(float4*)(g_agg + (size_t)gw * DD + lane * 4) = acc;
    }
}

// ---------------- launcher ----------------
extern "C" void kernel_launch(void* const* d_in, const int* in_sizes, int n_in,
                              void* d_out, int out_size) {
    const float* H     = (const float*)d_in[0];
    const int*   EI    = (const int*)d_in[1];     // int32! (JAX x64 disabled)
    const float* P     = (const float*)d_in[2];
    const float* DT    = (const float*)d_in[3];
    const float* W1    = (const float*)d_in[4];
    const float* W2    = (const float*)d_in[5];
    const float* W3    = (const float*)d_in[6];
    const float* W4    = (const float*)d_in[7];
    const float* Wv    = (const float*)d_in[8];
    const float* Woutw = (const float*)d_in[9];
    const float* Woutb = (const float*)d_in[10];
    const float* resw  = (const float*)d_in[11];
    const float* resb  = (const float*)d_in[12];
    const float* lng   = (const float*)d_in[13];
    const float* lnb   = (const float*)d_in[14];
    float* out = (float*)d_out;

    int n = in_sizes[0] / DD;   // 50000
    int e = in_sizes[2];        // 800000
    int gtiles = (n + 127) / 128;

    cudaFuncSetAttribute(k_gemm_v,   cudaFuncAttributeMaxDynamicSharedMemorySize, SM_GEMM);
    cudaFuncSetAttribute(k_gemm_out, cudaFuncAttributeMaxDynamicSharedMemorySize, SM_GEMM);

    k_prep<<<8 + (n + 255) / 256, 256>>>(W1, W2, W3, W4, n);
    k_hist<<<(e + 255) / 256, 256>>>(EI, e, n);
    k_scan<<<1, 1024>>>(n);
    k_scatter<<<(e + 255) / 256, 256>>>(EI, P, DT, e, n);
    k_gemm_v<<<gtiles, 256, SM_GEMM>>>(H, Wv, n);
    k_attn<<<(n + 3) / 4, 256>>>(n);
    k_gemm_out<<<gtiles, 256, SM_GEMM>>>(H, Woutw, Woutb, resw, resb, lng, lnb, out, n);
}

// round 15
// speedup vs baseline: 1.0860x; 1.0860x over previous
#include <cuda_runtime.h>
#include <cuda_bf16.h>
#include <cstdint>

#define NN 50000
#define EE 800000
#define DD 128
#define NHH 8

// ---------------- device scratch (no allocations allowed) ----------------
__device__ __align__(16) float g_V[NN * DD];     // H @ Wv^T
__device__ __align__(16) float g_agg[NN * DD];   // aggregated messages
__device__ __align__(16) float g_Adst[NN * NHH]; // H @ (W4 W1)^T
__device__ __align__(16) float g_Asrc[NN * NHH]; // H @ (W4 W2)^T
__device__ __align__(16) float g_Wa[16 * DD];    // rows 0-7: W4@W1, rows 8-15: W4@W2
__device__ float g_c[NHH];                       // W3 . W4[h]
__device__ int   g_deg[NN];
__device__ int   g_offs[NN + 1];
__device__ int   g_epos[EE];                     // per-edge slot within its dst bucket
__device__ __align__(16) float4 g_edge[EE];      // .x=src bits, .y=P, .z=De

// fast exp on fma/alu pipes (MUFU-free): exp(x) = 2^(x*log2e), |x| < 80
__device__ __forceinline__ float fexp(float x) {
    float t = x * 1.442695041f;
    float r = t + 12582912.0f;                   // 1.5*2^23 round-to-int magic
    int   i = __float_as_int(r) - 0x4B400000;
    float f = t - (r - 12582912.0f);             // [-0.5, 0.5]
    float c = f * 0.6931471806f;
    float p = fmaf(c, 0.008333333f, 0.041666667f);
    p = fmaf(c, p, 0.166666667f);
    p = fmaf(c, p, 0.5f);
    p = fmaf(c, p, 1.0f);
    p = fmaf(c, p, 1.0f);
    return p * __int_as_float((i + 127) << 23);
}

// ---------------- mma.sync bf16 split-precision GEMM machinery ----------------
// smem tiles: 128 rows x 64 bf16, pitch 72 bf16 (144B) -> fragment loads conflict-free
#define TPITCHB 144                    // bytes per tile row
#define T_AHI 0
#define T_ALO 18432
#define T_BHI 36864
#define T_BLO 55296
#define SM_GEMM 73728                  // 4 tiles; also >= 128*132*4 stage for k_out

__device__ __forceinline__ void mma16816(float* c, const uint32_t* a, const uint32_t* b) {
    asm volatile(
        "mma.sync.aligned.m16n8k16.row.col.f32.bf16.bf16.f32 "
        "{%0,%1,%2,%3}, {%4,%5,%6,%7}, {%8,%9}, {%0,%1,%2,%3};\n"
        : "+f"(c[0]), "+f"(c[1]), "+f"(c[2]), "+f"(c[3])
        : "r"(a[0]), "r"(a[1]), "r"(a[2]), "r"(a[3]), "r"(b[0]), "r"(b[1]));
}

// fetch 128x64 fp32 tile into 8 float4 regs/thread (256 threads)
__device__ __forceinline__ void g_fetch(float4* r, const float* __restrict__ G,
                                        int row0, int nrows, int kcol0) {
    int t = threadIdx.x;
    #pragma unroll
    for (int i = 0; i < 8; i++) {
        int f = t + i * 256;           // 2048 float4s
        int row = f >> 4, kq = f & 15;
        float4 v = make_float4(0.f, 0.f, 0.f, 0.f);
        if (row0 + row < nrows)
            v = *(const float4*)(G + (size_t)(row0 + row) * DD + kcol0 + kq * 4);
        r[i] = v;
    }
}

// convert regs -> bf16 hi/lo into padded smem
__device__ __forceinline__ void s_store(char* sm, int oh, int ol, const float4* r) {
    int t = threadIdx.x;
    #pragma unroll
    for (int i = 0; i < 8; i++) {
        int f = t + i * 256;
        int row = f >> 4, kq = f & 15;
        float xs[4] = {r[i].x, r[i].y, r[i].z, r[i].w};
        uint16_t hb[4], lb[4];
        #pragma unroll
        for (int q = 0; q < 4; q++) {
            __nv_bfloat16 h = __float2bfloat16(xs[q]);
            __nv_bfloat16 l = __float2bfloat16(xs[q] - __bfloat162float(h));
            hb[q] = __nv_bfloat16_raw(h).x;
            lb[q] = __nv_bfloat16_raw(l).x;
        }
        char* ph = sm + oh + row * TPITCHB + kq * 8;
        char* pl = sm + ol + row * TPITCHB + kq * 8;
        *(uint32_t*)ph       = (uint32_t)hb[1] << 16 | hb[0];
        *(uint32_t*)(ph + 4) = (uint32_t)hb[3] << 16 | hb[2];
        *(uint32_t*)pl       = (uint32_t)lb[1] << 16 | lb[0];
        *(uint32_t*)(pl + 4) = (uint32_t)lb[3] << 16 | lb[2];
    }
}

// one K=64 chunk of split MMAs; acc[2][8][4] per warp (warp tile 32x64)
__device__ __forceinline__ void mma_chunk(const char* sm, float acc[2][8][4],
                                          int warp_m, int warp_n, int lane) {
    int lr = lane >> 2, lc = lane & 3;
    #pragma unroll
    for (int ks = 0; ks < 4; ks++) {
        uint32_t ah[2][4], al[2][4], bh[8][2], bl[8][2];
        int kb = (ks * 16 + lc * 2) * 2;     // byte offset of k pair
        #pragma unroll
        for (int mt = 0; mt < 2; mt++) {
            int r = warp_m * 32 + mt * 16 + lr;
            const char* p = sm + T_AHI + r * TPITCHB + kb;
            ah[mt][0] = *(const uint32_t*)p;
            ah[mt][1] = *(const uint32_t*)(p + 8 * TPITCHB);
            ah[mt][2] = *(const uint32_t*)(p + 16);
            ah[mt][3] = *(const uint32_t*)(p + 8 * TPITCHB + 16);
            const char* q = sm + T_ALO + r * TPITCHB + kb;
            al[mt][0] = *(const uint32_t*)q;
            al[mt][1] = *(const uint32_t*)(q + 8 * TPITCHB);
            al[mt][2] = *(const uint32_t*)(q + 16);
            al[mt][3] = *(const uint32_t*)(q + 8 * TPITCHB + 16);
        }
        #pragma unroll
        for (int nt = 0; nt < 8; nt++) {
            int r = warp_n * 64 + nt * 8 + lr;
            const char* p = sm + T_BHI + r * TPITCHB + kb;
            bh[nt][0] = *(const uint32_t*)p;
            bh[nt][1] = *(const uint32_t*)(p + 16);
            const char* q = sm + T_BLO + r * TPITCHB + kb;
            bl[nt][0] = *(const uint32_t*)q;
            bl[nt][1] = *(const uint32_t*)(q + 16);
        }
        #pragma unroll
        for (int mt = 0; mt < 2; mt++)
            #pragma unroll
            for (int nt = 0; nt < 8; nt++) {
                mma16816(acc[mt][nt], ah[mt], bh[nt]);
                mma16816(acc[mt][nt], ah[mt], bl[nt]);
                mma16816(acc[mt][nt], al[mt], bh[nt]);
            }
    }
}

// ---------------- V = H @ Wv^T (tensor) + attn projection (fp32, L2-warm) ------
#define WAPITCH 130
__global__ void __launch_bounds__(256, 1) k_gemm_v(const float* __restrict__ H,
                                                   const float* __restrict__ Wv, int n) {
    extern __shared__ __align__(16) char sm[];
    __shared__ float s_Wa[16 * WAPITCH];
    int tid = threadIdx.x, wid = tid >> 5, lane = tid & 31;
    int warp_m = wid >> 1, warp_n = wid & 1;
    int m0 = blockIdx.x * 128;

    // stage Wa (16x128) into padded smem
    #pragma unroll
    for (int i = 0; i < 8; i++) {
        int f = tid + i * 256;    // 2048 elements
        int wr = f >> 7, k = f & 127;
        s_Wa[wr * WAPITCH + k] = g_Wa[wr * DD + k];
    }

    float acc[2][8][4];
    #pragma unroll
    for (int mt = 0; mt < 2; mt++)
        #pragma unroll
        for (int nt = 0; nt < 8; nt++)
            #pragma unroll
            for (int q = 0; q < 4; q++) acc[mt][nt][q] = 0.f;

    float4 ra[8], rb[8];
    g_fetch(ra, H, m0, n, 0);
    g_fetch(rb, Wv, 0, 128, 0);
    for (int c = 0; c < 2; c++) {
        if (c > 0) __syncthreads();          // mma of c-1 done before overwrite
        s_store(sm, T_AHI, T_ALO, ra);
        s_store(sm, T_BHI, T_BLO, rb);
        if (c < 1) {                         // prefetch next chunk (hidden behind mma)
            g_fetch(ra, H, m0, n, 64);
            g_fetch(rb, Wv, 0, 128, 64);
        }
        __syncthreads();
        mma_chunk(sm, acc, warp_m, warp_n, lane);
    }

    int lr = lane >> 2, lc = lane & 3;
    #pragma unroll
    for (int mt = 0; mt < 2; mt++) {
        int r0 = m0 + warp_m * 32 + mt * 16 + lr;
        #pragma unroll
        for (int nt = 0; nt < 8; nt++) {
            int cc = warp_n * 64 + nt * 8 + lc * 2;
            if (r0 < n)
                *(float2*)(g_V + (size_t)r0 * DD + cc) =
                    make_float2(acc[mt][nt][0], acc[mt][nt][1]);
            if (r0 + 8 < n)
                *(float2*)(g_V + (size_t)(r0 + 8) * DD + cc) =
                    make_float2(acc[mt][nt][2], acc[mt][nt][3]);
        }
    }

    // attention projection: thread pair (r, half) dots H row r (L2-warm) with 8 Wa rows
    int r = tid >> 1, half = tid & 1;
    int grow = m0 + r;
    if (grow < n) {
        float acc2[8];
        #pragma unroll
        for (int h = 0; h < 8; h++) acc2[h] = 0.f;
        const float4* hrow = (const float4*)(H + (size_t)grow * DD);
        const float* wbase = s_Wa + half * 8 * WAPITCH;
        #pragma unroll 4
        for (int kq = 0; kq < 32; kq++) {
            float4 hv = hrow[kq];
            #pragma unroll
            for (int h = 0; h < 8; h++) {
                const float* wr = wbase + h * WAPITCH + kq * 4;
                acc2[h] = fmaf(hv.x, wr[0], acc2[h]);
                acc2[h] = fmaf(hv.y, wr[1], acc2[h]);
                acc2[h] = fmaf(hv.z, wr[2], acc2[h]);
                acc2[h] = fmaf(hv.w, wr[3], acc2[h]);
            }
        }
        float* dp = half ? (g_Asrc + (size_t)grow * 8) : (g_Adst + (size_t)grow * 8);
        #pragma unroll
        for (int h = 0; h < 8; h++) dp[h] = acc2[h];
    }
}

// --------- out = LN([agg|H] @ [Wout|resw]^T + bias), K=256, tensor pipe ----------
__global__ void __launch_bounds__(256, 1) k_gemm_out(const float* __restrict__ H,
                                                     const float* __restrict__ Wout,
                                                     const float* __restrict__ Woutb,
                                                     const float* __restrict__ resw,
                                                     const float* __restrict__ resb,
                                                     const float* __restrict__ lng,
                                                     const float* __restrict__ lnb,
                                                     float* __restrict__ out, int n) {
    extern __shared__ __align__(16) char sm[];
    __shared__ __align__(16) float s_wb[128], s_g[128], s_b[128];
    int tid = threadIdx.x, wid = tid >> 5, lane = tid & 31;
    int warp_m = wid >> 1, warp_n = wid & 1;
    int m0 = blockIdx.x * 128;

    if (tid < 128) {
        s_wb[tid] = Woutb[tid] + resb[tid];
        s_g[tid] = lng[tid];
        s_b[tid] = lnb[tid];
    }

    float acc[2][8][4];
    #pragma unroll
    for (int mt = 0; mt < 2; mt++)
        #pragma unroll
        for (int nt = 0; nt < 8; nt++)
            #pragma unroll
            for (int q = 0; q < 4; q++) acc[mt][nt][q] = 0.f;

    const float* Asrc[4] = {g_agg, g_agg, H, H};
    const float* Bsrc[4] = {Wout, Wout, resw, resw};

    float4 ra[8], rb[8];
    g_fetch(ra, Asrc[0], m0, n, 0);
    g_fetch(rb, Bsrc[0], 0, 128, 0);
    for (int c = 0; c < 4; c++) {
        if (c > 0) __syncthreads();
        s_store(sm, T_AHI, T_ALO, ra);
        s_store(sm, T_BHI, T_BLO, rb);
        if (c < 3) {
            int kcol = ((c + 1) & 1) * 64;
            g_fetch(ra, Asrc[c + 1], m0, n, kcol);
            g_fetch(rb, Bsrc[c + 1], 0, 128, kcol);
        }
        __syncthreads();
        mma_chunk(sm, acc, warp_m, warp_n, lane);
    }
    __syncthreads();   // all mma reads done before stg overwrite

    // stage pre-LN rows in smem (reuse tile space), pitch 132 floats
    float* stg = (float*)sm;
    int lr = lane >> 2, lc = lane & 3;
    #pragma unroll
    for (int mt = 0; mt < 2; mt++) {
        int r0 = warp_m * 32 + mt * 16 + lr;
        #pragma unroll
        for (int nt = 0; nt < 8; nt++) {
            int cc = warp_n * 64 + nt * 8 + lc * 2;
            *(float2*)(stg + r0 * 132 + cc) = make_float2(acc[mt][nt][0], acc[mt][nt][1]);
            *(float2*)(stg + (r0 + 8) * 132 + cc) = make_float2(acc[mt][nt][2], acc[mt][nt][3]);
        }
    }
    __syncthreads();

    // LN: warp w handles rows [w*16, w*16+16)
    float4 wb4 = *(const float4*)(s_wb + lane * 4);
    float4 g4  = *(const float4*)(s_g + lane * 4);
    float4 b4  = *(const float4*)(s_b + lane * 4);
    for (int r = wid * 16; r < wid * 16 + 16; r++) {
        int grow = m0 + r;
        float4 v = *(const float4*)(stg + r * 132 + lane * 4);
        v.x += wb4.x; v.y += wb4.y; v.z += wb4.z; v.w += wb4.w;
        float s = v.x + v.y + v.z + v.w;
        float q = v.x * v.x + v.y * v.y + v.z * v.z + v.w * v.w;
        #pragma unroll
        for (int o = 16; o; o >>= 1) {
            s += __shfl_xor_sync(0xffffffffu, s, o);
            q += __shfl_xor_sync(0xffffffffu, q, o);
        }
        float mu  = s * (1.0f / 128.0f);
        float var = q * (1.0f / 128.0f) - mu * mu;
        float inv = rsqrtf(var + 1e-5f);
        if (grow < n) {
            float4 o4;
            o4.x = (v.x - mu) * inv * g4.x + b4.x;
            o4.y = (v.y - mu) * inv * g4.y + b4.y;
            o4.z = (v.z - mu) * inv * g4.z + b4.z;
            o4.w = (v.w - mu) * inv * g4.w + b4.w;
            *(float4*)(out + (size_t)grow * DD + lane * 4) = o4;
        }
    }
}

// ---------------- prep: blocks 0-7 compute Wa/c, blocks 8+ zero counters ------
__global__ void k_prep(const float* __restrict__ W1, const float* __restrict__ W2,
                       const float* __restrict__ W3, const float* __restrict__ W4,
                       int n) {
    if (blockIdx.x < 8) {
        int t = blockIdx.x * 256 + threadIdx.x;
        if (t < 16 * DD) {
            int h16 = t >> 7;
            int d = t & 127;
            const float* Wsel = (h16 < 8) ? W1 : W2;
            int h = h16 & 7;
            float s = 0.f;
            for (int k = 0; k < DD; k++)
                s = fmaf(W4[h * DD + k], Wsel[k * DD + d], s);
            g_Wa[t] = s;
        }
        if (t < NHH) {
            float s = 0.f;
            for (int j = 0; j < DD; j++)
                s = fmaf(W3[j], W4[t * DD + j], s);
            g_c[t] = s;
        }
    } else {
        int i = (blockIdx.x - 8) * 256 + threadIdx.x;
        if (i < n) g_deg[i] = 0;
    }
}

// edge_index is int32 (JAX x64 disabled; jnp.int64 silently downcasts).
// Record each edge's slot within its dst bucket -> scatter needs no atomics.
__global__ void k_hist(const int* __restrict__ ei, int e, int n) {
    int i = blockIdx.x * blockDim.x + threadIdx.x;
    if (i < e) {
        int dst = ei[e + i];
        dst = min(max(dst, 0), n - 1);
        g_epos[i] = atomicAdd(&g_deg[dst], 1);
    }
}

// single-block smem-tiled coarsened exclusive scan: g_deg -> g_offs
#define STILE 8192
__global__ void __launch_bounds__(1024) k_scan(int n) {
    __shared__ __align__(16) int sd[STILE];
    __shared__ int wsum[32];
    __shared__ int s_carry;
    int tid = threadIdx.x, lane = tid & 31, wid = tid >> 5;
    if (tid == 0) s_carry = 0;
    __syncthreads();

    for (int base = 0; base < n; base += STILE) {
        #pragma unroll
        for (int k = 0; k < 8; k++) {
            int i = base + tid + k * 1024;
            sd[tid + k * 1024] = (i < n) ? g_deg[i] : 0;
        }
        __syncthreads();

        int4 v0 = *(const int4*)&sd[tid * 8];
        int4 v1 = *(const int4*)&sd[tid * 8 + 4];
        int loc[8] = {v0.x, v0.y, v0.z, v0.w, v1.x, v1.y, v1.z, v1.w};
        int s = 0;
        #pragma unroll
        for (int k = 0; k < 8; k++) s += loc[k];

        int x = s;
        #pragma unroll
        for (int o = 1; o < 32; o <<= 1) {
            int y = __shfl_up_sync(0xffffffffu, x, o);
            if (lane >= o) x += y;
        }
        if (lane == 31) wsum[wid] = x;
        __syncthreads();
        if (wid == 0) {
            int w = wsum[lane];
            #pragma unroll
            for (int o = 1; o < 32; o <<= 1) {
                int y = __shfl_up_sync(0xffffffffu, w, o);
                if (lane >= o) w += y;
            }
            wsum[lane] = w;
        }
        __syncthreads();

        int run = x - s + (wid ? wsum[wid - 1] : 0) + s_carry;
        int4 o0, o1;
        o0.x = run; run += loc[0];
        o0.y = run; run += loc[1];
        o0.z = run; run += loc[2];
        o0.w = run; run += loc[3];
        o1.x = run; run += loc[4];
        o1.y = run; run += loc[5];
        o1.z = run; run += loc[6];
        o1.w = run; run += loc[7];
        *(int4*)&sd[tid * 8]     = o0;
        *(int4*)&sd[tid * 8 + 4] = o1;
        __syncthreads();
        if (tid == 1023) s_carry = run;

        #pragma unroll
        for (int k = 0; k < 8; k++) {
            int i = base + tid + k * 1024;
            if (i < n) g_offs[i] = sd[tid + k * 1024];
        }
        __syncthreads();
    }
    if (tid == 0) g_offs[n] = s_carry;
}

// atomic-free scatter: slot from g_epos; single 16B packed store per edge
__global__ void k_scatter(const int* __restrict__ ei,
                          const float* __restrict__ P, const float* __restrict__ DT,
                          int e, int n) {
    int i = blockIdx.x * blockDim.x + threadIdx.x;
    if (i < e) {
        int src = ei[i];
        int dst = ei[e + i];
        src = min(max(src, 0), n - 1);
        dst = min(max(dst, 0), n - 1);
        int j = g_offs[dst] + g_epos[i];
        if (j >= 0 && j < e)
            g_edge[j] = make_float4(__int_as_float(src), P[i], DT[i], 0.f);
    }
}

// ------- per-dst-node attention + aggregation (one warp per node, MUFU-free) -----
__global__ void __launch_bounds__(256) k_attn(int n) {
    int gw = (int)((blockIdx.x * blockDim.x + threadIdx.x) >> 5);
    int lane = threadIdx.x & 31;
    if (gw >= n) return;
    int beg = g_offs[gw], end = g_offs[gw + 1];

    float adst[8], cv[8];
    #pragma unroll
    for (int h = 0; h < 8; h++) { adst[h] = g_Adst[(size_t)gw * 8 + h]; cv[h] = g_c[h]; }

    // pass 1: fexp(logit) + per-head sum (softmax shift algebraically free;
    // logits O(10) << 80, fexp cannot overflow). No exp caching.
    float sm8[8];
    #pragma unroll
    for (int h = 0; h < 8; h++) sm8[h] = 0.f;
    for (int j = beg + lane; j < end; j += 32) {
        float4 ed = g_edge[j];
        int s = __float_as_int(ed.x);
        float p = ed.y, dt = ed.z;
        const float4* as4 = (const float4*)(g_Asrc + (size_t)s * 8);
        float4 a0 = as4[0], a1 = as4[1];
        float asv[8] = {a0.x, a0.y, a0.z, a0.w, a1.x, a1.y, a1.z, a1.w};
        #pragma unroll
        for (int h = 0; h < 8; h++) {
            float l = adst[h] + asv[h] + p * cv[h] + dt;
            l = (l >= 0.f) ? l : 0.2f * l;
            sm8[h] += fexp(l);
        }
    }
    #pragma unroll
    for (int h = 0; h < 8; h++)
        #pragma unroll
        for (int o = 16; o; o >>= 1)
            sm8[h] += __shfl_xor_sync(0xffffffffu, sm8[h], o);

    // pass 2: recompute exp per edge for own head; lane covers dims [lane*4,+4),
    // head = lane>>2 (4 lanes share a head -> Asrc scalar load broadcasts per quad)
    int h = lane >> 2;
    float dsel = (h & 4) ? ((h & 2) ? ((h & 1) ? sm8[7] : sm8[6]) : ((h & 1) ? sm8[5] : sm8[4]))
                         : ((h & 2) ? ((h & 1) ? sm8[3] : sm8[2]) : ((h & 1) ? sm8[1] : sm8[0]));
    float ri = __fdividef(1.0f, dsel + 1e-12f);
    float adst_h = adst[0], cv_h = cv[0];
    #pragma unroll
    for (int q = 1; q < 8; q++) {
        if (h == q) { adst_h = adst[q]; cv_h = cv[q]; }
    }

    float4 acc = make_float4(0.f, 0.f, 0.f, 0.f);
    const float4* Vv = (const float4*)g_V;
    #pragma unroll 4
    for (int j = beg; j < end; j++) {
        float4 ed = g_edge[j];
        int s = __float_as_int(ed.x);
        float asv = g_Asrc[(size_t)s * 8 + h];
        float l = adst_h + asv + ed.y * cv_h + ed.z;
        l = (l >= 0.f) ? l : 0.2f * l;
        float a = fexp(l) * ri;
        float4 v = Vv[(size_t)s * 32 + lane];
        acc.x = fmaf(a, v.x, acc.x);
        acc.y = fmaf(a, v.y, acc.y);
        acc.z = fmaf(a, v.z, acc.z);
        acc.w = fmaf(a, v.w, acc.w);
    }
    *(float4*)(g_agg + (size_t)gw * DD + lane * 4) = acc;
}

// ---------------- launcher ----------------
extern "C" void kernel_launch(void* const* d_in, const int* in_sizes, int n_in,
                              void* d_out, int out_size) {
    const float* H     = (const float*)d_in[0];
    const int*   EI    = (const int*)d_in[1];     // int32! (JAX x64 disabled)
    const float* P     = (const float*)d_in[2];
    const float* DT    = (const float*)d_in[3];
    const float* W1    = (const float*)d_in[4];
    const float* W2    = (const float*)d_in[5];
    const float* W3    = (const float*)d_in[6];
    const float* W4    = (const float*)d_in[7];
    const float* Wv    = (const float*)d_in[8];
    const float* Woutw = (const float*)d_in[9];
    const float* Woutb = (const float*)d_in[10];
    const float* resw  = (const float*)d_in[11];
    const float* resb  = (const float*)d_in[12];
    const float* lng   = (const float*)d_in[13];
    const float* lnb   = (const float*)d_in[14];
    float* out = (float*)d_out;

    int n = in_sizes[0] / DD;   // 50000
    int e = in_sizes[2];        // 800000
    int gtiles = (n + 127) / 128;

    cudaFuncSetAttribute(k_gemm_v,   cudaFuncAttributeMaxDynamicSharedMemorySize, SM_GEMM);
    cudaFuncSetAttribute(k_gemm_out, cudaFuncAttributeMaxDynamicSharedMemorySize, SM_GEMM);

    k_prep<<<8 + (n + 255) / 256, 256>>>(W1, W2, W3, W4, n);
    k_hist<<<(e + 255) / 256, 256>>>(EI, e, n);
    k_scan<<<1, 1024>>>(n);
    k_scatter<<<(e + 255) / 256, 256>>>(EI, P, DT, e, n);
    k_gemm_v<<<gtiles, 256, SM_GEMM>>>(H, Wv, n);
    k_attn<<<(n + 7) / 8, 256>>>(n);
    k_gemm_out<<<gtiles, 256, SM_GEMM>>>(H, Woutw, Woutb, resw, resb, lng, lnb, out, n);
}